// round 2
// baseline (speedup 1.0000x reference)
#include <cuda_runtime.h>
#include <math.h>
#include <float.h>

#define BB 16
#define SS 64
#define MM 2048
#define DD 256
#define TK 8
#define OV 512
#define NBLK 128
#define SCALE 0.0625f

// state (re-initialized every launch; no runtime allocs)
__device__ float g_ovl[BB*OV*DD];     // copy-on-write overlay rows (8MB)
__device__ int   g_slot[BB*MM];       // -1 or overlay slot
__device__ int   g_ovcnt[BB];
__device__ float g_qk[SS*BB*DD];      // scale*(Wk^T Wq xt + Wk^T bq), all steps
__device__ float g_gx[SS*BB*DD];      // Wu1 xt + bu, all steps
__device__ float g_AT[DD*DD];         // [j][d] = scale*(Wk^T Wq)[d][j]... stored j-major
__device__ float g_avec[DD];
__device__ float g_WuT1[DD*DD];
__device__ float g_WuT2[DD*DD];
__device__ float g_WvT[DD*DD];
__device__ float g_scores[BB*MM];
__device__ float g_pmax[NBLK*BB];
__device__ float g_psum[NBLK*BB];
__device__ float g_partial[NBLK*BB*DD];  // 2MB

// ---------------- init ----------------

__global__ void p_trans(const float* __restrict__ Wv, const float* __restrict__ Wu){
  __shared__ float tile[32][33];
  int which = blockIdx.z;
  const float* src; int stride; float* dst;
  if (which==0){ src=Wv; stride=DD;   dst=g_WvT;  }
  else if (which==1){ src=Wu; stride=2*DD; dst=g_WuT1; }
  else { src=Wu+DD; stride=2*DD; dst=g_WuT2; }
  int bi=blockIdx.x*32, bj=blockIdx.y*32;
  int tx=threadIdx.x, ty=threadIdx.y;
  #pragma unroll
  for (int k=0;k<32;k+=8) tile[ty+k][tx] = src[(size_t)(bi+ty+k)*stride + bj+tx];
  __syncthreads();
  #pragma unroll
  for (int k=0;k<32;k+=8) dst[(size_t)(bj+ty+k)*DD + bi+tx] = tile[tx][ty+k];
}

__global__ void p_A(const float* __restrict__ Wq, const float* __restrict__ Wk,
                    const float* __restrict__ bq){
  __shared__ float col[DD];
  int j = blockIdx.x, tid = threadIdx.x;
  col[tid] = (j < DD) ? Wq[(size_t)tid*DD + j] : bq[tid];
  __syncthreads();
  float acc = 0.f;
  #pragma unroll 4
  for (int i=0;i<DD;i++) acc = fmaf(Wk[(size_t)i*DD+tid], col[i], acc);
  if (j < DD) g_AT[j*DD+tid] = acc*SCALE;
  else        g_avec[tid]    = acc*SCALE;
}

__global__ void p_slot(){
  int i = blockIdx.x*256 + threadIdx.x;
  if (i < BB*MM) g_slot[i] = -1;
  if (i < BB)    g_ovcnt[i] = 0;
}

__global__ void p_qk(const float* __restrict__ x, const float* __restrict__ bu){
  __shared__ float xs[BB][DD];
  int t = blockIdx.x, which = blockIdx.y, tid = threadIdx.x;
  for (int i=tid;i<BB*DD;i+=256){ int b=i>>8, j=i&255; xs[b][j] = x[((size_t)b*SS+t)*DD + j]; }
  __syncthreads();
  const float* W = (which==0) ? g_AT : g_WuT1;
  float acc[BB];
  #pragma unroll
  for (int b=0;b<BB;b++) acc[b]=0.f;
  for (int j=0;j<DD;j++){
    float w = W[j*DD+tid];
    #pragma unroll
    for (int b=0;b<BB;b++) acc[b] = fmaf(w, xs[b][j], acc[b]);
  }
  if (which==0){
    float av = g_avec[tid];
    #pragma unroll
    for (int b=0;b<BB;b++) g_qk[((size_t)t*BB+b)*DD+tid] = acc[b]+av;
  } else {
    float bb = bu[tid];
    #pragma unroll
    for (int b=0;b<BB;b++) g_gx[((size_t)t*BB+b)*DD+tid] = acc[b]+bb;
  }
}

// ---------------- per-step ----------------

// scores + dirty fix + per-block softmax partials
__global__ void k1(const float* __restrict__ base, int t){
  __shared__ float rows[16][257];
  __shared__ float qks[16][257];
  __shared__ float sc[16][17];
  __shared__ int dlist[256];
  __shared__ int dcnt;
  int blk = blockIdx.x, m0 = blk*16, tid = threadIdx.x;
  for (int i=tid;i<16*DD;i+=256){ int r=i>>8, j=i&255; rows[r][j] = base[(size_t)(m0+r)*DD + j]; }
  const float* qkt = g_qk + (size_t)t*BB*DD;
  for (int i=tid;i<16*DD;i+=256){ int b=i>>8, j=i&255; qks[b][j] = qkt[i]; }
  if (tid==0) dcnt = 0;
  __syncthreads();
  int b = tid&15, r = tid>>4;
  float acc = 0.f;
  #pragma unroll 8
  for (int j=0;j<DD;j++) acc = fmaf(rows[r][j], qks[b][j], acc);
  sc[b][r] = acc;
  int s = g_slot[b*MM + m0 + r];
  if (s >= 0){ int p = atomicAdd(&dcnt,1); dlist[p] = (b<<16)|(r<<12)|s; }
  __syncthreads();
  int wid = tid>>5, lane = tid&31;
  int dn = dcnt;
  for (int e=wid; e<dn; e+=8){
    int pk = dlist[e]; int eb = pk>>16, er = (pk>>12)&15, es = pk&0xfff;
    const float* ov = g_ovl + ((size_t)eb*OV + es)*DD;
    float a2 = 0.f;
    #pragma unroll
    for (int k=0;k<8;k++) a2 = fmaf(ov[lane+32*k], qks[eb][lane+32*k], a2);
    #pragma unroll
    for (int off=16; off; off>>=1) a2 += __shfl_xor_sync(0xffffffffu, a2, off);
    if (lane==0) sc[eb][er] = a2;
  }
  __syncthreads();
  g_scores[b*MM + m0 + r] = sc[b][r];
  if (tid < 16){
    float mx = -FLT_MAX;
    #pragma unroll
    for (int rr=0;rr<16;rr++) mx = fmaxf(mx, sc[tid][rr]);
    float sm = 0.f;
    #pragma unroll
    for (int rr=0;rr<16;rr++) sm += expf(sc[tid][rr]-mx);
    g_pmax[blk*16+tid] = mx;
    g_psum[blk*16+tid] = sm;
  }
}

// combine softmax stats; attn for own rows; h partials (base + dirty corrections)
__global__ void k3(const float* __restrict__ base, int t){
  __shared__ float rows[16][257];
  __shared__ float attn_s[16][17];
  __shared__ float spart[16][DD];
  __shared__ float red2[16][17];
  __shared__ float sgm[16], sginv[16];
  __shared__ int dlist[256];
  __shared__ int dcnt;
  int blk = blockIdx.x, m0 = blk*16, tid = threadIdx.x;
  for (int i=tid;i<16*DD;i+=256){ int r=i>>8, j=i&255; rows[r][j] = base[(size_t)(m0+r)*DD + j]; }
  if (tid==0) dcnt = 0;
  int cb = tid>>4, cp = tid&15;
  float lm = -FLT_MAX;
  for (int k=cp;k<NBLK;k+=16) lm = fmaxf(lm, g_pmax[k*16+cb]);
  red2[cb][cp] = lm; __syncthreads();
  if (cp==0){ float m2=red2[cb][0]; for (int z=1;z<16;z++) m2=fmaxf(m2,red2[cb][z]); sgm[cb]=m2; }
  __syncthreads();
  float ls = 0.f;
  for (int k=cp;k<NBLK;k+=16) ls += g_psum[k*16+cb]*expf(g_pmax[k*16+cb]-sgm[cb]);
  red2[cb][cp] = ls; __syncthreads();
  if (cp==0){ float s2=0.f; for (int z=0;z<16;z++) s2+=red2[cb][z]; sginv[cb]=1.f/s2; }
  __syncthreads();
  int b = tid&15, r = tid>>4;
  attn_s[b][r] = expf(g_scores[b*MM + m0 + r] - sgm[b]) * sginv[b];
  int s = g_slot[b*MM + m0 + r];
  if (s >= 0){ int p = atomicAdd(&dcnt,1); dlist[p] = (b<<16)|(r<<12)|s; }
  __syncthreads();
  float acc[16];
  #pragma unroll
  for (int z=0;z<16;z++) acc[z]=0.f;
  #pragma unroll 4
  for (int rr=0;rr<16;rr++){
    float rv = rows[rr][tid];
    #pragma unroll
    for (int bz=0;bz<16;bz++) acc[bz] = fmaf(attn_s[bz][rr], rv, acc[bz]);
  }
  #pragma unroll
  for (int bz=0;bz<16;bz++) spart[bz][tid] = acc[bz];
  __syncthreads();
  int wid = tid>>5, lane = tid&31;
  int dn = dcnt;
  for (int e=wid; e<dn; e+=8){
    int pk = dlist[e]; int eb = pk>>16, er = (pk>>12)&15, es = pk&0xfff;
    const float* ov = g_ovl + ((size_t)eb*OV + es)*DD;
    float a = attn_s[eb][er];
    #pragma unroll
    for (int k=0;k<8;k++){ int d = lane+32*k; atomicAdd(&spart[eb][d], a*(ov[d]-rows[er][d])); }
  }
  __syncthreads();
  for (int i=tid;i<16*DD;i+=256) g_partial[(size_t)blk*16*DD + i] = ((float*)spart)[i];
}

// reduce -> h -> memout -> out; gate; top8; slot assign; row update
__global__ void k4(const float* __restrict__ base, const float* __restrict__ x,
                   const float* __restrict__ bv, float* __restrict__ out, int t){
  __shared__ float hs[DD], ms[DD], xt_s[DD], gate_s[DD];
  __shared__ float ss[MM];
  __shared__ float rv[8]; __shared__ int ri[8];
  __shared__ int idxs[TK], prevs[TK], slots[TK];
  int b = blockIdx.x, tid = threadIdx.x;
  float h = 0.f;
  #pragma unroll 4
  for (int k2=0;k2<NBLK;k2++) h += g_partial[((size_t)k2*16+b)*DD + tid];
  hs[tid] = h;
  xt_s[tid] = x[((size_t)b*SS+t)*DD + tid];
  for (int i=tid;i<MM;i+=256) ss[i] = g_scores[b*MM + i];
  __syncthreads();
  float mo = 0.f;
  #pragma unroll 4
  for (int j=0;j<DD;j++) mo = fmaf(g_WvT[j*DD+tid], hs[j], mo);
  mo += bv[tid];
  ms[tid] = mo;
  out[((size_t)b*SS+t)*DD + tid] = mo;
  __syncthreads();
  float gp = g_gx[((size_t)t*BB+b)*DD + tid];
  #pragma unroll 4
  for (int j=0;j<DD;j++) gp = fmaf(g_WuT2[j*DD+tid], ms[j], gp);
  gate_s[tid] = 1.f/(1.f+expf(-gp));
  int wid = tid>>5, lane = tid&31;
  for (int k2=0;k2<TK;k2++){
    float v = -FLT_MAX; int bi = MM;
    #pragma unroll
    for (int m=tid;m<MM;m+=256){ float s2 = ss[m]; if (s2 > v){ v=s2; bi=m; } }
    #pragma unroll
    for (int off=16; off; off>>=1){
      float ov2 = __shfl_xor_sync(0xffffffffu, v, off);
      int   oi  = __shfl_xor_sync(0xffffffffu, bi, off);
      if (ov2 > v || (ov2==v && oi<bi)){ v=ov2; bi=oi; }
    }
    if (lane==0){ rv[wid]=v; ri[wid]=bi; }
    __syncthreads();
    if (tid==0){
      float bv2 = rv[0]; int bi2 = ri[0];
      for (int w=1;w<8;w++){ if (rv[w]>bv2 || (rv[w]==bv2 && ri[w]<bi2)){ bv2=rv[w]; bi2=ri[w]; } }
      idxs[k2] = bi2; ss[bi2] = -FLT_MAX;
    }
    __syncthreads();
  }
  if (tid==0){
    int cnt = g_ovcnt[b];
    for (int i=0;i<TK;i++){
      int row = idxs[i]; int s = g_slot[b*MM+row];
      prevs[i] = s;
      if (s < 0){ s = cnt++; g_slot[b*MM+row] = s; }
      slots[i] = s;
    }
    g_ovcnt[b] = cnt;
  }
  __syncthreads();
  float g = gate_s[tid];
  float xd = xt_s[tid];
  #pragma unroll
  for (int i=0;i<TK;i++){
    int row = idxs[i];
    float old = (prevs[i] < 0) ? base[(size_t)row*DD + tid]
                               : g_ovl[((size_t)b*OV + prevs[i])*DD + tid];
    g_ovl[((size_t)b*OV + slots[i])*DD + tid] = old + g*(xd - old);
  }
}

// ---------------- launch ----------------

extern "C" void kernel_launch(void* const* d_in, const int* in_sizes, int n_in,
                              void* d_out, int out_size){
  const float* x      = (const float*)d_in[0];
  const float* memory = (const float*)d_in[1];
  const float* Wq     = (const float*)d_in[2];
  const float* bq     = (const float*)d_in[3];
  const float* Wk     = (const float*)d_in[4];
  // bk (d_in[5]) contributes only a softmax-invariant constant -> dropped
  const float* Wv     = (const float*)d_in[6];
  const float* bv     = (const float*)d_in[7];
  const float* Wu     = (const float*)d_in[8];
  const float* bu     = (const float*)d_in[9];
  float* out = (float*)d_out;

  p_trans<<<dim3(8,8,3), dim3(32,8)>>>(Wv, Wu);
  p_A<<<DD+1, 256>>>(Wq, Wk, bq);
  p_slot<<<128, 256>>>();
  p_qk<<<dim3(SS,2), 256>>>(x, bu);

  for (int t=0; t<SS; t++){
    k1<<<NBLK, 256>>>(memory, t);
    k3<<<NBLK, 256>>>(memory, t);
    k4<<<BB, 256>>>(memory, x, bv, out, t);
  }
}